// round 15
// baseline (speedup 1.0000x reference)
#include <cuda_runtime.h>
#include <cuda_fp16.h>
#include <math.h>
#include <stdint.h>

// Problem constants
#define N_NODES 50000
#define N_EDGES 800000
#define TOT_E   850000
#define HD      128
#define NB_SCAN 49            // ceil(50000/1024)
#define NB_FILL 3125          // ceil(800000/256)

// ---------------- device scratch --------------------------------------------
__device__ float g_bufA[(size_t)N_NODES * HD];   // fp16 xw ping
__device__ float g_bufB[(size_t)N_NODES * HD];   // fp16 xw pong
__device__ int   g_src[N_EDGES];
__device__ int   g_dst[N_EDGES];
__device__ int   g_flag;
__device__ int   g_cnt[N_NODES];
__device__ int   g_off2[N_NODES + 1];
__device__ int   g_csr[TOT_E];
__device__ int   g_bpub[NB_SCAN];
__device__ float g_inv[N_NODES];
__device__ float g_s[N_NODES];
__device__ float g_d[N_NODES];
__device__ float g_esc[TOT_E];          // fallback only (deg > 64)
__device__ unsigned short g_wperm[5][128 * 128];  // fp16 fragment-permuted weights

// ---------------- warp MMA helper (fp16 inputs, fp32 accum) -------------------
__device__ __forceinline__ void mma16816(float* d, const uint32_t* a, const uint32_t* b) {
    asm volatile(
        "mma.sync.aligned.m16n8k16.row.col.f32.f16.f16.f32 "
        "{%0,%1,%2,%3}, {%4,%5,%6,%7}, {%8,%9}, {%0,%1,%2,%3};"
        : "+f"(d[0]), "+f"(d[1]), "+f"(d[2]), "+f"(d[3])
        : "r"(a[0]), "r"(a[1]), "r"(a[2]), "r"(a[3]), "r"(b[0]), "r"(b[1]));
}

// ---------------- pre: zero counts + init lookback + detect edge dtype --------
__global__ void k_pre(const unsigned int* __restrict__ w) {
    int i = blockIdx.x * 1024 + threadIdx.x;
    if (i < N_NODES) g_cnt[i] = 0;
    if (blockIdx.x == 1 && threadIdx.x < NB_SCAN) g_bpub[threadIdx.x] = -1;
    if (blockIdx.x == 0) {
        __shared__ int sflag;
        if (threadIdx.x == 0) sflag = 0;
        __syncthreads();
        if (w[2 * threadIdx.x + 1] != 0u) atomicOr(&sflag, 1);
        __syncthreads();
        if (threadIdx.x == 0) g_flag = sflag;
    }
}

// ---------------- fused: edge convert+count (y=0) | weight conversion (y=1) --
__global__ void k_convert_count(const void* __restrict__ ei,
                                const float* __restrict__ W1, const float* __restrict__ Wg1,
                                const float* __restrict__ W2, const float* __restrict__ Wg2,
                                const float* __restrict__ Wo) {
    if (blockIdx.y == 0) {
        int e = blockIdx.x * blockDim.x + threadIdx.x;
        if (e >= N_EDGES) return;
        int s, d;
        if (g_flag) {
            const int* p = (const int*)ei;
            s = p[e]; d = p[N_EDGES + e];
        } else {
            const long long* p = (const long long*)ei;
            s = (int)p[e]; d = (int)p[N_EDGES + e];
        }
        g_src[e] = s;
        g_dst[e] = d;
        atomicAdd(&g_cnt[d], 1);
    } else {
        int idx = blockIdx.x * blockDim.x + threadIdx.x;
        if (idx >= 4 * 16384 + 8192) return;
        int wsel, base, BN;
        if (idx < 16384)      { wsel = 0; base = 0;      BN = 128; }
        else if (idx < 32768) { wsel = 1; base = 16384;  BN = 128; }
        else if (idx < 49152) { wsel = 2; base = 32768;  BN = 128; }
        else if (idx < 65536) { wsel = 3; base = 49152;  BN = 128; }
        else                  { wsel = 4; base = 65536;  BN = 64;  }
        const float* W = (wsel == 0) ? W1 : (wsel == 1) ? Wg1 : (wsel == 2) ? W2
                       : (wsel == 3) ? Wg2 : Wo;
        int li = idx - base;
        int k = li / BN, n = li % BN;
        __half h = __float2half_rn(W[li]);
        int nt = n >> 3, kt = k >> 4, kk = k & 15;
        int reg = kk >> 3, klo = kk & 7;
        int lane = (n & 7) * 4 + (klo >> 1);
        int slot = ((nt * 8 + kt) * 32 + lane) * 2 + reg;
        int pos = slot * 2 + (kk & 1);
        g_wperm[wsel][pos] = __half_as_ushort(h);
    }
}

// ---------------- standalone scan + finalize (decoupled lookback) -------------
__global__ void __launch_bounds__(256)
k_scan() {
    __shared__ int sdat[256];
    __shared__ int s_prefix;
    int t = threadIdx.x;
    int blk = blockIdx.x;
    int base = blk * 1024 + t * 4;
    int v[4];
    int lsum = 0;
#pragma unroll
    for (int q = 0; q < 4; ++q) {
        int i = base + q;
        v[q] = (i < N_NODES) ? g_cnt[i] + 1 : 0;   // +1 = self loop
        lsum += v[q];
    }
    sdat[t] = lsum;
    __syncthreads();
    for (int off = 1; off < 256; off <<= 1) {
        int xx = (t >= off) ? sdat[t - off] : 0;
        __syncthreads();
        sdat[t] += xx;
        __syncthreads();
    }
    int incl = sdat[t];
    if (t == 255) *(volatile int*)&g_bpub[blk] = incl;
    if (t < 32) {
        int pre = 0;
        for (int j = t; j < blk; j += 32) {
            int vv;
            do { vv = *(volatile int*)&g_bpub[j]; } while (vv == -1);
            pre += vv;
        }
#pragma unroll
        for (int o = 16; o; o >>= 1) pre += __shfl_xor_sync(0xffffffffu, pre, o);
        if (t == 0) s_prefix = pre;
    }
    __syncthreads();
    int b = s_prefix + incl - lsum;
#pragma unroll
    for (int q = 0; q < 4; ++q) {
        int i = base + q;
        if (i < N_NODES) {
            g_off2[i] = b;
            g_csr[b] = i;          // self loop
            g_cnt[i] = b + 1;      // fill cursor
            g_inv[i] = rsqrtf((float)v[q]);
            if (i == N_NODES - 1) g_off2[N_NODES] = b + v[q];
            b += v[q];
        }
    }
}

// ---------------- GEMM core: A frags in smem, B frags via L1 (__ldg) ----------
template <int BN, bool IN16, bool OUT16>
__device__ __forceinline__ void gemm_core(
    int row0, uint32_t* ah,
    const void* __restrict__ Xv, const unsigned short* __restrict__ wperm,
    const float* __restrict__ bias, void* __restrict__ Yv, int M,
    const float* __restrict__ a_s, const float* __restrict__ a_d) {
    constexpr int NT = BN / 16;
    int tid  = threadIdx.x;
    int wid  = tid >> 5;
    int lane = tid & 31;

    // A tile -> fragment-permuted fp16 smem
#pragma unroll
    for (int it = 0; it < 16; ++it) {
        int idx = it * 256 + tid;
        int r = idx >> 5;
        int c = (idx & 31) * 4;
        int gr = row0 + r;
        uint32_t hi0 = 0, hi1 = 0;
        if (gr < M) {
            if (IN16) {
                uint2 u = ((const uint2*)Xv)[(size_t)gr * 32 + (idx & 31)];
                hi0 = u.x; hi1 = u.y;
            } else {
                float4 v = ((const float4*)Xv)[(size_t)gr * 32 + (idx & 31)];
                __half2 h0 = __floats2half2_rn(v.x, v.y);
                __half2 h1 = __floats2half2_rn(v.z, v.w);
                hi0 = *reinterpret_cast<uint32_t*>(&h0);
                hi1 = *reinterpret_cast<uint32_t*>(&h1);
            }
        }
        int mt = r >> 4, rr = r & 15;
        int kt = c >> 4, cc = c & 15;
        int reg = ((cc >> 3) << 1) | (rr >> 3);
        int ln0 = (rr & 7) * 4 + ((cc & 7) >> 1);
        int base = (mt * 8 + kt) * 32;
        ah[(base + ln0) * 4 + reg]     = hi0;
        ah[(base + ln0 + 1) * 4 + reg] = hi1;
    }
    __syncthreads();

    int wm = wid & 3;
    int wn = wid >> 2;
    float acc[2][NT][4];
#pragma unroll
    for (int i = 0; i < 2; ++i)
#pragma unroll
        for (int j = 0; j < NT; ++j)
#pragma unroll
            for (int q = 0; q < 4; ++q) acc[i][j][q] = 0.f;

    const uint4* Ah = (const uint4*)ah;
    const uint2* Bg = (const uint2*)wperm;     // L1-resident after first k-step
#pragma unroll
    for (int kt = 0; kt < 8; ++kt) {
        uint4 a0 = Ah[((wm * 2 + 0) * 8 + kt) * 32 + lane];
        uint4 a1 = Ah[((wm * 2 + 1) * 8 + kt) * 32 + lane];
        uint2 b[NT];
#pragma unroll
        for (int j = 0; j < NT; ++j)
            b[j] = __ldg(&Bg[((wn * NT + j) * 8 + kt) * 32 + lane]);
#pragma unroll
        for (int j = 0; j < NT; ++j) {
            mma16816(acc[0][j], (const uint32_t*)&a0, (const uint32_t*)&b[j]);
            mma16816(acc[1][j], (const uint32_t*)&a1, (const uint32_t*)&b[j]);
        }
    }

    int rbase = row0 + wm * 32 + (lane >> 2);
    int cbase = wn * NT * 8 + (lane & 3) * 2;
#pragma unroll
    for (int i = 0; i < 2; ++i) {
        int r = rbase + i * 16;
#pragma unroll
        for (int j = 0; j < NT; ++j) {
            int cc = cbase + j * 8;
            float bx = 0.f, by = 0.f;
            if (bias) { bx = bias[cc]; by = bias[cc + 1]; }
            if (OUT16) {
                __half* Y = (__half*)Yv;
                if (r < M)
                    *(__half2*)&Y[(size_t)r * BN + cc] =
                        __floats2half2_rn(acc[i][j][0] + bx, acc[i][j][1] + by);
                if (r + 8 < M)
                    *(__half2*)&Y[(size_t)(r + 8) * BN + cc] =
                        __floats2half2_rn(acc[i][j][2] + bx, acc[i][j][3] + by);
            } else {
                float* Y = (float*)Yv;
                if (r < M) {
                    float2 v0 = make_float2(acc[i][j][0] + bx, acc[i][j][1] + by);
                    *(float2*)&Y[(size_t)r * BN + cc] = v0;
                }
                if (r + 8 < M) {
                    float2 v1 = make_float2(acc[i][j][2] + bx, acc[i][j][3] + by);
                    *(float2*)&Y[(size_t)(r + 8) * BN + cc] = v1;
                }
            }
        }
    }

    if (a_s) {
        float ps[2][2] = {{0.f, 0.f}, {0.f, 0.f}};
        float pd[2][2] = {{0.f, 0.f}, {0.f, 0.f}};
#pragma unroll
        for (int i = 0; i < 2; ++i)
#pragma unroll
            for (int j = 0; j < NT; ++j) {
                int cc = cbase + j * 8;
                float as0 = a_s[cc], as1 = a_s[cc + 1];
                float ad0 = a_d[cc], ad1 = a_d[cc + 1];
                ps[i][0] += acc[i][j][0] * as0 + acc[i][j][1] * as1;
                pd[i][0] += acc[i][j][0] * ad0 + acc[i][j][1] * ad1;
                ps[i][1] += acc[i][j][2] * as0 + acc[i][j][3] * as1;
                pd[i][1] += acc[i][j][2] * ad0 + acc[i][j][3] * ad1;
            }
#pragma unroll
        for (int i = 0; i < 2; ++i)
#pragma unroll
            for (int h = 0; h < 2; ++h) {
                float s = ps[i][h], d = pd[i][h];
                s += __shfl_xor_sync(0xffffffffu, s, 1);
                s += __shfl_xor_sync(0xffffffffu, s, 2);
                d += __shfl_xor_sync(0xffffffffu, d, 1);
                d += __shfl_xor_sync(0xffffffffu, d, 2);
                if ((lane & 3) == 0) {
                    int r = row0 + wm * 32 + i * 16 + h * 8 + (lane >> 2);
                    if (r < M) {
                        atomicAdd(&g_s[r], s);
                        atomicAdd(&g_d[r], d);
                    }
                }
            }
    }
}

// ---------------- standalone GEMM kernel ---------------------------------------
template <int BN, bool IN16, bool OUT16>
__global__ void __launch_bounds__(256)
tc_gemm(const void* __restrict__ Xv, const unsigned short* __restrict__ wperm,
        const float* __restrict__ bias, void* __restrict__ Yv, int M,
        const float* __restrict__ a_s, const float* __restrict__ a_d) {
    __shared__ uint32_t ah[8192];   // 32 KB A fragments
    gemm_core<BN, IN16, OUT16>(blockIdx.x * 128, ah, Xv, wperm, bias, Yv, M, a_s, a_d);
}

// ---------------- co-launched fill_edges (blocks 0..3124) + K1 GEMM ------------
__global__ void __launch_bounds__(256)
k_fillK1(const float* __restrict__ x, void* __restrict__ Yv, int M) {
    __shared__ uint32_t ah[8192];
    if (blockIdx.x < NB_FILL) {
        int e = blockIdx.x * blockDim.x + threadIdx.x;
        if (e < N_EDGES) {
            int pos = atomicAdd(&g_cnt[g_dst[e]], 1);
            g_csr[pos] = g_src[e];
        }
    } else {
        gemm_core<128, false, true>((blockIdx.x - NB_FILL) * 128, ah,
                                    x, g_wperm[0], nullptr, Yv, M, nullptr, nullptr);
    }
}

// ---------------- half-warp gather helpers -------------------------------------
struct F8 { float v[8]; };

__device__ __forceinline__ F8 load_row8(const uint4* xw4, int s, int gl) {
    uint4 u = xw4[(size_t)s * 16 + gl];
    F8 r;
    float2 f;
    f = __half22float2(*reinterpret_cast<__half2*>(&u.x)); r.v[0] = f.x; r.v[1] = f.y;
    f = __half22float2(*reinterpret_cast<__half2*>(&u.y)); r.v[2] = f.x; r.v[3] = f.y;
    f = __half22float2(*reinterpret_cast<__half2*>(&u.z)); r.v[4] = f.x; r.v[5] = f.y;
    f = __half22float2(*reinterpret_cast<__half2*>(&u.w)); r.v[6] = f.x; r.v[7] = f.y;
    return r;
}

__device__ __forceinline__ void store_row8(void* out, int w, int gl,
                                           const float* a, bool out16) {
    if (out16) {
        uint4 u;
        __half2 h;
        h = __floats2half2_rn(a[0], a[1]); u.x = *reinterpret_cast<uint32_t*>(&h);
        h = __floats2half2_rn(a[2], a[3]); u.y = *reinterpret_cast<uint32_t*>(&h);
        h = __floats2half2_rn(a[4], a[5]); u.z = *reinterpret_cast<uint32_t*>(&h);
        h = __floats2half2_rn(a[6], a[7]); u.w = *reinterpret_cast<uint32_t*>(&h);
        ((uint4*)out)[(size_t)w * 16 + gl] = u;
    } else {
        float* o = (float*)out + (size_t)w * 128 + gl * 8;
        *(float4*)o       = make_float4(a[0], a[1], a[2], a[3]);
        *(float4*)(o + 4) = make_float4(a[4], a[5], a[6], a[7]);
    }
}

// ---------------- GCN aggregate: half-warp per node ----------------------------
template <bool OUT16>
__global__ void gcn_agg(const __half* __restrict__ xw,
                        const float* __restrict__ bias,
                        void* __restrict__ out) {
    int gwarp = (blockIdx.x * blockDim.x + threadIdx.x) >> 5;
    int lane = threadIdx.x & 31;
    int grp = lane >> 4, gl = lane & 15;
    int w = gwarp * 2 + grp;
    if (w >= N_NODES) return;
    if (gl == 0) { g_s[w] = 0.f; g_d[w] = 0.f; }
    int beg = g_off2[w], end = g_off2[w + 1];
    float invd = g_inv[w];
    const uint4* xw4 = (const uint4*)xw;
    float acc[8] = {0.f, 0.f, 0.f, 0.f, 0.f, 0.f, 0.f, 0.f};
    int p = beg;
    for (; p + 1 < end; p += 2) {
        int s0 = g_csr[p], s1 = g_csr[p + 1];
        float c0 = invd * g_inv[s0];
        float c1 = invd * g_inv[s1];
        F8 v0 = load_row8(xw4, s0, gl);
        F8 v1 = load_row8(xw4, s1, gl);
#pragma unroll
        for (int q = 0; q < 8; ++q) acc[q] += c0 * v0.v[q] + c1 * v1.v[q];
    }
    if (p < end) {
        int s0 = g_csr[p];
        float c0 = invd * g_inv[s0];
        F8 v0 = load_row8(xw4, s0, gl);
#pragma unroll
        for (int q = 0; q < 8; ++q) acc[q] += c0 * v0.v[q];
    }
    const float4* b4 = (const float4*)bias;
    float4 b0 = b4[gl * 2], b1 = b4[gl * 2 + 1];
    acc[0] = fmaxf(acc[0] + b0.x, 0.f); acc[1] = fmaxf(acc[1] + b0.y, 0.f);
    acc[2] = fmaxf(acc[2] + b0.z, 0.f); acc[3] = fmaxf(acc[3] + b0.w, 0.f);
    acc[4] = fmaxf(acc[4] + b1.x, 0.f); acc[5] = fmaxf(acc[5] + b1.y, 0.f);
    acc[6] = fmaxf(acc[6] + b1.z, 0.f); acc[7] = fmaxf(acc[7] + b1.w, 0.f);
    store_row8(out, w, gl, acc, OUT16);
}

// ---------------- GAT aggregate: half-warp per node, register-cached -----------
template <bool OUT16>
__global__ void gat_agg(const __half* __restrict__ xw,
                        const float* __restrict__ bias,
                        void* __restrict__ out) {
    int gwarp = (blockIdx.x * blockDim.x + threadIdx.x) >> 5;
    int lane = threadIdx.x & 31;
    int grp = lane >> 4, gl = lane & 15;
    int shbase = grp << 4;
    unsigned hmask = 0xFFFFu << shbase;    // exact half-warp convergence group
    int w = gwarp * 2 + grp;
    if (w >= N_NODES) return;
    int beg = g_off2[w], end = g_off2[w + 1];
    int deg = end - beg;
    float dd = g_d[w];
    const uint4* xw4 = (const uint4*)xw;
    float acc[8] = {0.f, 0.f, 0.f, 0.f, 0.f, 0.f, 0.f, 0.f};

    if (deg <= 64) {
        int sc[4];
        float ex[4];
        float m = -1e30f;
#pragma unroll
        for (int rr = 0; rr < 4; ++rr) {
            int p = beg + gl + 16 * rr;
            sc[rr] = 0; ex[rr] = -1e30f;
            if (p < end) {
                sc[rr] = g_csr[p];
                float t = g_s[sc[rr]] + dd;
                ex[rr] = (t > 0.f) ? t : 0.2f * t;
            }
            m = fmaxf(m, ex[rr]);
        }
#pragma unroll
        for (int o = 8; o; o >>= 1) m = fmaxf(m, __shfl_xor_sync(hmask, m, o));
        float sum = 0.f;
#pragma unroll
        for (int rr = 0; rr < 4; ++rr) {
            int p = beg + gl + 16 * rr;
            ex[rr] = (p < end) ? __expf(ex[rr] - m) : 0.f;
            sum += ex[rr];
        }
#pragma unroll
        for (int o = 8; o; o >>= 1) sum += __shfl_xor_sync(hmask, sum, o);
        float invden = 1.0f / sum;

        int idx = 0;
        for (; idx + 1 < deg; idx += 2) {
            int r0 = idx >> 4,       l0 = (idx & 15) + shbase;
            int r1 = (idx + 1) >> 4, l1 = ((idx + 1) & 15) + shbase;
            float e0 = (r0 == 0) ? ex[0] : (r0 == 1) ? ex[1] : (r0 == 2) ? ex[2] : ex[3];
            int   c0 = (r0 == 0) ? sc[0] : (r0 == 1) ? sc[1] : (r0 == 2) ? sc[2] : sc[3];
            float e1 = (r1 == 0) ? ex[0] : (r1 == 1) ? ex[1] : (r1 == 2) ? ex[2] : ex[3];
            int   c1 = (r1 == 0) ? sc[0] : (r1 == 1) ? sc[1] : (r1 == 2) ? sc[2] : sc[3];
            float wa = __shfl_sync(hmask, e0, l0) * invden;
            int   sa = __shfl_sync(hmask, c0, l0);
            float wb = __shfl_sync(hmask, e1, l1) * invden;
            int   sb = __shfl_sync(hmask, c1, l1);
            F8 va = load_row8(xw4, sa, gl);
            F8 vb = load_row8(xw4, sb, gl);
#pragma unroll
            for (int q = 0; q < 8; ++q) acc[q] += wa * va.v[q] + wb * vb.v[q];
        }
        if (idx < deg) {
            int r0 = idx >> 4, l0 = (idx & 15) + shbase;
            float e0 = (r0 == 0) ? ex[0] : (r0 == 1) ? ex[1] : (r0 == 2) ? ex[2] : ex[3];
            int   c0 = (r0 == 0) ? sc[0] : (r0 == 1) ? sc[1] : (r0 == 2) ? sc[2] : sc[3];
            float wa = __shfl_sync(hmask, e0, l0) * invden;
            int   sa = __shfl_sync(hmask, c0, l0);
            F8 va = load_row8(xw4, sa, gl);
#pragma unroll
            for (int q = 0; q < 8; ++q) acc[q] += wa * va.v[q];
        }
    } else {
        float m = -1e30f;
        for (int p = beg + gl; p < end; p += 16) {
            int s = g_csr[p];
            float e = g_s[s] + dd;
            e = (e > 0.f) ? e : 0.2f * e;
            g_esc[p] = e;
            m = fmaxf(m, e);
        }
#pragma unroll
        for (int o = 8; o; o >>= 1) m = fmaxf(m, __shfl_xor_sync(hmask, m, o));
        float sum = 0.f;
        for (int p = beg + gl; p < end; p += 16) {
            float e = __expf(g_esc[p] - m);
            g_esc[p] = e;
            sum += e;
        }
#pragma unroll
        for (int o = 8; o; o >>= 1) sum += __shfl_xor_sync(hmask, sum, o);
        float invden = 1.0f / sum;
        __syncwarp(hmask);
        for (int p = beg; p < end; ++p) {
            int s = g_csr[p];
            float wgt = g_esc[p] * invden;
            F8 v = load_row8(xw4, s, gl);
#pragma unroll
            for (int q = 0; q < 8; ++q) acc[q] += wgt * v.v[q];
        }
    }

    const float4* b4 = (const float4*)bias;
    float4 b0 = b4[gl * 2], b1 = b4[gl * 2 + 1];
    acc[0] = fmaxf(acc[0] + b0.x, 0.f); acc[1] = fmaxf(acc[1] + b0.y, 0.f);
    acc[2] = fmaxf(acc[2] + b0.z, 0.f); acc[3] = fmaxf(acc[3] + b0.w, 0.f);
    acc[4] = fmaxf(acc[4] + b1.x, 0.f); acc[5] = fmaxf(acc[5] + b1.y, 0.f);
    acc[6] = fmaxf(acc[6] + b1.z, 0.f); acc[7] = fmaxf(acc[7] + b1.w, 0.f);
    store_row8(out, w, gl, acc, OUT16);
}

// ---------------- host launch ---------------------------------------------------
extern "C" void kernel_launch(void* const* d_in, const int* in_sizes, int n_in,
                              void* d_out, int out_size) {
    const float* x     = (const float*)d_in[0];
    const void*  ei    = d_in[1];
    const float* W1    = (const float*)d_in[2];
    const float* b1    = (const float*)d_in[3];
    const float* Wg1   = (const float*)d_in[4];
    const float* asrc1 = (const float*)d_in[5];
    const float* adst1 = (const float*)d_in[6];
    const float* bg1   = (const float*)d_in[7];
    const float* W2    = (const float*)d_in[8];
    const float* b2    = (const float*)d_in[9];
    const float* Wg2   = (const float*)d_in[10];
    const float* asrc2 = (const float*)d_in[11];
    const float* adst2 = (const float*)d_in[12];
    const float* bg2   = (const float*)d_in[13];
    const float* Wo    = (const float*)d_in[14];
    const float* bo    = (const float*)d_in[15];

    float* out_h = (float*)d_out;
    float* out_z = out_h + (size_t)N_NODES * HD;

    float *pA = nullptr, *pB = nullptr;
    unsigned short* pW = nullptr;
    cudaGetSymbolAddress((void**)&pA, g_bufA);
    cudaGetSymbolAddress((void**)&pB, g_bufB);
    cudaGetSymbolAddress((void**)&pW, g_wperm);
    __half* pA16 = (__half*)pA;
    __half* pB16 = (__half*)pB;
    const size_t WSTRIDE = 128 * 128;

    const int TB = 256;
    dim3 nb_edge((N_EDGES + TB - 1) / TB);
    dim3 nb_hw((N_NODES + 15) / 16);
    dim3 nb_gemm((N_NODES + 127) / 128);

    // CSR build + weight conversion
    k_pre<<<NB_SCAN, 1024>>>((const unsigned int*)ei);
    k_convert_count<<<dim3(nb_edge.x, 2), TB>>>(ei, W1, Wg1, W2, Wg2, Wo);
    k_scan<<<NB_SCAN, TB>>>();

    // fill_edges (3125 blocks) co-launched with K1 GEMM (391 blocks)
    k_fillK1<<<NB_FILL + nb_gemm.x, TB>>>(x, pA16, N_NODES);

    // Layer 1 agg: GCN (zeroes g_s/g_d for K2's att epilogue)
    gcn_agg<true><<<nb_hw, TB>>>(pA16, b1, pB16);

    // K2: xw2 = agg1 @ Wg1 (+ att dots)
    tc_gemm<128, true, true><<<nb_gemm, TB>>>(pB16, pW + WSTRIDE, nullptr, pA16, N_NODES, asrc1, adst1);
    gat_agg<true><<<nb_hw, TB>>>(pA16, bg1, pB16);

    // K3: xw3 = agg2 @ W2
    tc_gemm<128, true, true><<<nb_gemm, TB>>>(pB16, pW + 2 * WSTRIDE, nullptr, pA16, N_NODES, nullptr, nullptr);
    gcn_agg<true><<<nb_hw, TB>>>(pA16, b2, pB16);

    // K4: xw4 = agg3 @ Wg2 (+ att dots)
    tc_gemm<128, true, true><<<nb_gemm, TB>>>(pB16, pW + 3 * WSTRIDE, nullptr, pA16, N_NODES, asrc2, adst2);
    gat_agg<false><<<nb_hw, TB>>>(pA16, bg2, out_h);

    // K5: z = h @ Wo + bo (fp32 in/out)
    tc_gemm<64, false, false><<<nb_gemm, TB>>>(out_h, pW + 4 * WSTRIDE, bo, out_z, N_NODES, nullptr, nullptr);
}

// round 16
// speedup vs baseline: 1.0364x; 1.0364x over previous
#include <cuda_runtime.h>
#include <cuda_fp16.h>
#include <math.h>
#include <stdint.h>

// Problem constants
#define N_NODES 50000
#define N_EDGES 800000
#define TOT_E   850000
#define HD      128
#define NB_SCAN 49            // ceil(50000/1024)
#define NB_E4   782           // ceil(800000/1024) : 4 edges per thread

// ---------------- device scratch --------------------------------------------
__device__ float g_bufA[(size_t)N_NODES * HD];   // fp16 xw ping
__device__ float g_bufB[(size_t)N_NODES * HD];   // fp16 xw pong
__device__ int   g_src[N_EDGES];
__device__ int   g_dst[N_EDGES];
__device__ int   g_flag;
__device__ int   g_cnt[N_NODES];
__device__ int   g_off2[N_NODES + 1];
__device__ int   g_csr[TOT_E];
__device__ int   g_bpub[NB_SCAN];
__device__ float g_inv[N_NODES];
__device__ float g_s[N_NODES];
__device__ float g_d[N_NODES];
__device__ float g_esc[TOT_E];          // fallback only (deg > 64)
__device__ unsigned short g_wperm[5][128 * 128];  // fp16 fragment-permuted weights

// ---------------- warp MMA helper (fp16 inputs, fp32 accum) -------------------
__device__ __forceinline__ void mma16816(float* d, const uint32_t* a, const uint32_t* b) {
    asm volatile(
        "mma.sync.aligned.m16n8k16.row.col.f32.f16.f16.f32 "
        "{%0,%1,%2,%3}, {%4,%5,%6,%7}, {%8,%9}, {%0,%1,%2,%3};"
        : "+f"(d[0]), "+f"(d[1]), "+f"(d[2]), "+f"(d[3])
        : "r"(a[0]), "r"(a[1]), "r"(a[2]), "r"(a[3]), "r"(b[0]), "r"(b[1]));
}

// ---------------- pre: zero counts + init lookback + detect edge dtype --------
__global__ void k_pre(const unsigned int* __restrict__ w) {
    int i = blockIdx.x * 1024 + threadIdx.x;
    if (i < N_NODES) g_cnt[i] = 0;
    if (blockIdx.x == 1 && threadIdx.x < NB_SCAN) g_bpub[threadIdx.x] = -1;
    if (blockIdx.x == 0) {
        __shared__ int sflag;
        if (threadIdx.x == 0) sflag = 0;
        __syncthreads();
        if (w[2 * threadIdx.x + 1] != 0u) atomicOr(&sflag, 1);
        __syncthreads();
        if (threadIdx.x == 0) g_flag = sflag;
    }
}

// ---------------- fused: edge convert+count x4 (y=0) | weight conv (y=1) ------
__global__ void k_convert_count(const void* __restrict__ ei,
                                const float* __restrict__ W1, const float* __restrict__ Wg1,
                                const float* __restrict__ W2, const float* __restrict__ Wg2,
                                const float* __restrict__ Wo) {
    if (blockIdx.y == 0) {
        int e0 = (blockIdx.x * blockDim.x + threadIdx.x) * 4;
#pragma unroll
        for (int q = 0; q < 4; ++q) {
            int e = e0 + q;
            if (e >= N_EDGES) break;
            int s, d;
            if (g_flag) {
                const int* p = (const int*)ei;
                s = p[e]; d = p[N_EDGES + e];
            } else {
                const long long* p = (const long long*)ei;
                s = (int)p[e]; d = (int)p[N_EDGES + e];
            }
            g_src[e] = s;
            g_dst[e] = d;
            atomicAdd(&g_cnt[d], 1);
        }
    } else {
        int idx = blockIdx.x * blockDim.x + threadIdx.x;
        if (idx >= 4 * 16384 + 8192) return;
        int wsel, base, BN;
        if (idx < 16384)      { wsel = 0; base = 0;      BN = 128; }
        else if (idx < 32768) { wsel = 1; base = 16384;  BN = 128; }
        else if (idx < 49152) { wsel = 2; base = 32768;  BN = 128; }
        else if (idx < 65536) { wsel = 3; base = 49152;  BN = 128; }
        else                  { wsel = 4; base = 65536;  BN = 64;  }
        const float* W = (wsel == 0) ? W1 : (wsel == 1) ? Wg1 : (wsel == 2) ? W2
                       : (wsel == 3) ? Wg2 : Wo;
        int li = idx - base;
        int k = li / BN, n = li % BN;
        __half h = __float2half_rn(W[li]);
        int nt = n >> 3, kt = k >> 4, kk = k & 15;
        int reg = kk >> 3, klo = kk & 7;
        int lane = (n & 7) * 4 + (klo >> 1);
        int slot = ((nt * 8 + kt) * 32 + lane) * 2 + reg;
        int pos = slot * 2 + (kk & 1);
        g_wperm[wsel][pos] = __half_as_ushort(h);
    }
}

__global__ void k_fill_edges4() {
    int e0 = (blockIdx.x * blockDim.x + threadIdx.x) * 4;
#pragma unroll
    for (int q = 0; q < 4; ++q) {
        int e = e0 + q;
        if (e >= N_EDGES) break;
        int pos = atomicAdd(&g_cnt[g_dst[e]], 1);
        g_csr[pos] = g_src[e];
    }
}

// ---------------- GEMM core: A frags in smem, B frags via L1 (__ldg) ----------
template <int BN, bool IN16, bool OUT16>
__device__ __forceinline__ void gemm_core(
    int row0, uint32_t* ah,
    const void* __restrict__ Xv, const unsigned short* __restrict__ wperm,
    const float* __restrict__ bias, void* __restrict__ Yv, int M,
    const float* __restrict__ a_s, const float* __restrict__ a_d) {
    constexpr int NT = BN / 16;
    int tid  = threadIdx.x;
    int wid  = tid >> 5;
    int lane = tid & 31;

    // A tile -> fragment-permuted fp16 smem
#pragma unroll
    for (int it = 0; it < 16; ++it) {
        int idx = it * 256 + tid;
        int r = idx >> 5;
        int c = (idx & 31) * 4;
        int gr = row0 + r;
        uint32_t hi0 = 0, hi1 = 0;
        if (gr < M) {
            if (IN16) {
                uint2 u = ((const uint2*)Xv)[(size_t)gr * 32 + (idx & 31)];
                hi0 = u.x; hi1 = u.y;
            } else {
                float4 v = ((const float4*)Xv)[(size_t)gr * 32 + (idx & 31)];
                __half2 h0 = __floats2half2_rn(v.x, v.y);
                __half2 h1 = __floats2half2_rn(v.z, v.w);
                hi0 = *reinterpret_cast<uint32_t*>(&h0);
                hi1 = *reinterpret_cast<uint32_t*>(&h1);
            }
        }
        int mt = r >> 4, rr = r & 15;
        int kt = c >> 4, cc = c & 15;
        int reg = ((cc >> 3) << 1) | (rr >> 3);
        int ln0 = (rr & 7) * 4 + ((cc & 7) >> 1);
        int base = (mt * 8 + kt) * 32;
        ah[(base + ln0) * 4 + reg]     = hi0;
        ah[(base + ln0 + 1) * 4 + reg] = hi1;
    }
    __syncthreads();

    int wm = wid & 3;
    int wn = wid >> 2;
    float acc[2][NT][4];
#pragma unroll
    for (int i = 0; i < 2; ++i)
#pragma unroll
        for (int j = 0; j < NT; ++j)
#pragma unroll
            for (int q = 0; q < 4; ++q) acc[i][j][q] = 0.f;

    const uint4* Ah = (const uint4*)ah;
    const uint2* Bg = (const uint2*)wperm;     // L1-resident after first k-step
#pragma unroll
    for (int kt = 0; kt < 8; ++kt) {
        uint4 a0 = Ah[((wm * 2 + 0) * 8 + kt) * 32 + lane];
        uint4 a1 = Ah[((wm * 2 + 1) * 8 + kt) * 32 + lane];
        uint2 b[NT];
#pragma unroll
        for (int j = 0; j < NT; ++j)
            b[j] = __ldg(&Bg[((wn * NT + j) * 8 + kt) * 32 + lane]);
#pragma unroll
        for (int j = 0; j < NT; ++j) {
            mma16816(acc[0][j], (const uint32_t*)&a0, (const uint32_t*)&b[j]);
            mma16816(acc[1][j], (const uint32_t*)&a1, (const uint32_t*)&b[j]);
        }
    }

    int rbase = row0 + wm * 32 + (lane >> 2);
    int cbase = wn * NT * 8 + (lane & 3) * 2;
#pragma unroll
    for (int i = 0; i < 2; ++i) {
        int r = rbase + i * 16;
#pragma unroll
        for (int j = 0; j < NT; ++j) {
            int cc = cbase + j * 8;
            float bx = 0.f, by = 0.f;
            if (bias) { bx = bias[cc]; by = bias[cc + 1]; }
            if (OUT16) {
                __half* Y = (__half*)Yv;
                if (r < M)
                    *(__half2*)&Y[(size_t)r * BN + cc] =
                        __floats2half2_rn(acc[i][j][0] + bx, acc[i][j][1] + by);
                if (r + 8 < M)
                    *(__half2*)&Y[(size_t)(r + 8) * BN + cc] =
                        __floats2half2_rn(acc[i][j][2] + bx, acc[i][j][3] + by);
            } else {
                float* Y = (float*)Yv;
                if (r < M) {
                    float2 v0 = make_float2(acc[i][j][0] + bx, acc[i][j][1] + by);
                    *(float2*)&Y[(size_t)r * BN + cc] = v0;
                }
                if (r + 8 < M) {
                    float2 v1 = make_float2(acc[i][j][2] + bx, acc[i][j][3] + by);
                    *(float2*)&Y[(size_t)(r + 8) * BN + cc] = v1;
                }
            }
        }
    }

    if (a_s) {
        float ps[2][2] = {{0.f, 0.f}, {0.f, 0.f}};
        float pd[2][2] = {{0.f, 0.f}, {0.f, 0.f}};
#pragma unroll
        for (int i = 0; i < 2; ++i)
#pragma unroll
            for (int j = 0; j < NT; ++j) {
                int cc = cbase + j * 8;
                float as0 = a_s[cc], as1 = a_s[cc + 1];
                float ad0 = a_d[cc], ad1 = a_d[cc + 1];
                ps[i][0] += acc[i][j][0] * as0 + acc[i][j][1] * as1;
                pd[i][0] += acc[i][j][0] * ad0 + acc[i][j][1] * ad1;
                ps[i][1] += acc[i][j][2] * as0 + acc[i][j][3] * as1;
                pd[i][1] += acc[i][j][2] * ad0 + acc[i][j][3] * ad1;
            }
#pragma unroll
        for (int i = 0; i < 2; ++i)
#pragma unroll
            for (int h = 0; h < 2; ++h) {
                float s = ps[i][h], d = pd[i][h];
                s += __shfl_xor_sync(0xffffffffu, s, 1);
                s += __shfl_xor_sync(0xffffffffu, s, 2);
                d += __shfl_xor_sync(0xffffffffu, d, 1);
                d += __shfl_xor_sync(0xffffffffu, d, 2);
                if ((lane & 3) == 0) {
                    int r = row0 + wm * 32 + i * 16 + h * 8 + (lane >> 2);
                    if (r < M) {
                        atomicAdd(&g_s[r], s);
                        atomicAdd(&g_d[r], d);
                    }
                }
            }
    }
}

// ---------------- standalone GEMM kernel ---------------------------------------
template <int BN, bool IN16, bool OUT16>
__global__ void __launch_bounds__(256)
tc_gemm(const void* __restrict__ Xv, const unsigned short* __restrict__ wperm,
        const float* __restrict__ bias, void* __restrict__ Yv, int M,
        const float* __restrict__ a_s, const float* __restrict__ a_d) {
    __shared__ uint32_t ah[8192];   // 32 KB A fragments
    gemm_core<BN, IN16, OUT16>(blockIdx.x * 128, ah, Xv, wperm, bias, Yv, M, a_s, a_d);
}

// ---------------- co-launched scan (blocks 0..48) + K1 GEMM (blocks 49..) ------
__global__ void __launch_bounds__(256)
k_scanK1(const float* __restrict__ x, void* __restrict__ Yv, int M) {
    __shared__ uint32_t ah[8192];
    if (blockIdx.x < NB_SCAN) {
        __shared__ int sdat[256];
        __shared__ int s_prefix;
        int t = threadIdx.x;
        int blk = blockIdx.x;
        int base = blk * 1024 + t * 4;
        int v[4];
        int lsum = 0;
#pragma unroll
        for (int q = 0; q < 4; ++q) {
            int i = base + q;
            v[q] = (i < N_NODES) ? g_cnt[i] + 1 : 0;   // +1 = self loop
            lsum += v[q];
        }
        sdat[t] = lsum;
        __syncthreads();
        for (int off = 1; off < 256; off <<= 1) {
            int xx = (t >= off) ? sdat[t - off] : 0;
            __syncthreads();
            sdat[t] += xx;
            __syncthreads();
        }
        int incl = sdat[t];
        if (t == 255) *(volatile int*)&g_bpub[blk] = incl;
        if (t < 32) {
            int pre = 0;
            for (int j = t; j < blk; j += 32) {
                int vv;
                do { vv = *(volatile int*)&g_bpub[j]; } while (vv == -1);
                pre += vv;
            }
#pragma unroll
            for (int o = 16; o; o >>= 1) pre += __shfl_xor_sync(0xffffffffu, pre, o);
            if (t == 0) s_prefix = pre;
        }
        __syncthreads();
        int b = s_prefix + incl - lsum;
#pragma unroll
        for (int q = 0; q < 4; ++q) {
            int i = base + q;
            if (i < N_NODES) {
                g_off2[i] = b;
                g_csr[b] = i;          // self loop
                g_cnt[i] = b + 1;      // fill cursor
                g_inv[i] = rsqrtf((float)v[q]);
                if (i == N_NODES - 1) g_off2[N_NODES] = b + v[q];
                b += v[q];
            }
        }
    } else {
        gemm_core<128, false, true>((blockIdx.x - NB_SCAN) * 128, ah,
                                    x, g_wperm[0], nullptr, Yv, M, nullptr, nullptr);
    }
}

// ---------------- half-warp gather helpers -------------------------------------
struct F8 { float v[8]; };

__device__ __forceinline__ F8 load_row8(const uint4* xw4, int s, int gl) {
    uint4 u = xw4[(size_t)s * 16 + gl];
    F8 r;
    float2 f;
    f = __half22float2(*reinterpret_cast<__half2*>(&u.x)); r.v[0] = f.x; r.v[1] = f.y;
    f = __half22float2(*reinterpret_cast<__half2*>(&u.y)); r.v[2] = f.x; r.v[3] = f.y;
    f = __half22float2(*reinterpret_cast<__half2*>(&u.z)); r.v[4] = f.x; r.v[5] = f.y;
    f = __half22float2(*reinterpret_cast<__half2*>(&u.w)); r.v[6] = f.x; r.v[7] = f.y;
    return r;
}

__device__ __forceinline__ void store_row8(void* out, int w, int gl,
                                           const float* a, bool out16) {
    if (out16) {
        uint4 u;
        __half2 h;
        h = __floats2half2_rn(a[0], a[1]); u.x = *reinterpret_cast<uint32_t*>(&h);
        h = __floats2half2_rn(a[2], a[3]); u.y = *reinterpret_cast<uint32_t*>(&h);
        h = __floats2half2_rn(a[4], a[5]); u.z = *reinterpret_cast<uint32_t*>(&h);
        h = __floats2half2_rn(a[6], a[7]); u.w = *reinterpret_cast<uint32_t*>(&h);
        ((uint4*)out)[(size_t)w * 16 + gl] = u;
    } else {
        float* o = (float*)out + (size_t)w * 128 + gl * 8;
        *(float4*)o       = make_float4(a[0], a[1], a[2], a[3]);
        *(float4*)(o + 4) = make_float4(a[4], a[5], a[6], a[7]);
    }
}

// ---------------- GCN aggregate: half-warp per node ----------------------------
template <bool OUT16>
__global__ void gcn_agg(const __half* __restrict__ xw,
                        const float* __restrict__ bias,
                        void* __restrict__ out) {
    int gwarp = (blockIdx.x * blockDim.x + threadIdx.x) >> 5;
    int lane = threadIdx.x & 31;
    int grp = lane >> 4, gl = lane & 15;
    int w = gwarp * 2 + grp;
    if (w >= N_NODES) return;
    if (gl == 0) { g_s[w] = 0.f; g_d[w] = 0.f; }
    int beg = g_off2[w], end = g_off2[w + 1];
    float invd = g_inv[w];
    const uint4* xw4 = (const uint4*)xw;
    float acc[8] = {0.f, 0.f, 0.f, 0.f, 0.f, 0.f, 0.f, 0.f};
    int p = beg;
    for (; p + 1 < end; p += 2) {
        int s0 = g_csr[p], s1 = g_csr[p + 1];
        float c0 = invd * g_inv[s0];
        float c1 = invd * g_inv[s1];
        F8 v0 = load_row8(xw4, s0, gl);
        F8 v1 = load_row8(xw4, s1, gl);
#pragma unroll
        for (int q = 0; q < 8; ++q) acc[q] += c0 * v0.v[q] + c1 * v1.v[q];
    }
    if (p < end) {
        int s0 = g_csr[p];
        float c0 = invd * g_inv[s0];
        F8 v0 = load_row8(xw4, s0, gl);
#pragma unroll
        for (int q = 0; q < 8; ++q) acc[q] += c0 * v0.v[q];
    }
    const float4* b4 = (const float4*)bias;
    float4 b0 = b4[gl * 2], b1 = b4[gl * 2 + 1];
    acc[0] = fmaxf(acc[0] + b0.x, 0.f); acc[1] = fmaxf(acc[1] + b0.y, 0.f);
    acc[2] = fmaxf(acc[2] + b0.z, 0.f); acc[3] = fmaxf(acc[3] + b0.w, 0.f);
    acc[4] = fmaxf(acc[4] + b1.x, 0.f); acc[5] = fmaxf(acc[5] + b1.y, 0.f);
    acc[6] = fmaxf(acc[6] + b1.z, 0.f); acc[7] = fmaxf(acc[7] + b1.w, 0.f);
    store_row8(out, w, gl, acc, OUT16);
}

// ---------------- GAT aggregate: half-warp per node, register-cached -----------
template <bool OUT16>
__global__ void gat_agg(const __half* __restrict__ xw,
                        const float* __restrict__ bias,
                        void* __restrict__ out) {
    int gwarp = (blockIdx.x * blockDim.x + threadIdx.x) >> 5;
    int lane = threadIdx.x & 31;
    int grp = lane >> 4, gl = lane & 15;
    int shbase = grp << 4;
    unsigned hmask = 0xFFFFu << shbase;    // exact half-warp convergence group
    int w = gwarp * 2 + grp;
    if (w >= N_NODES) return;
    int beg = g_off2[w], end = g_off2[w + 1];
    int deg = end - beg;
    float dd = g_d[w];
    const uint4* xw4 = (const uint4*)xw;
    float acc[8] = {0.f, 0.f, 0.f, 0.f, 0.f, 0.f, 0.f, 0.f};

    if (deg <= 64) {
        int sc[4];
        float ex[4];
        float m = -1e30f;
#pragma unroll
        for (int rr = 0; rr < 4; ++rr) {
            int p = beg + gl + 16 * rr;
            sc[rr] = 0; ex[rr] = -1e30f;
            if (p < end) {
                sc[rr] = g_csr[p];
                float t = g_s[sc[rr]] + dd;
                ex[rr] = (t > 0.f) ? t : 0.2f * t;
            }
            m = fmaxf(m, ex[rr]);
        }
#pragma unroll
        for (int o = 8; o; o >>= 1) m = fmaxf(m, __shfl_xor_sync(hmask, m, o));
        float sum = 0.f;
#pragma unroll
        for (int rr = 0; rr < 4; ++rr) {
            int p = beg + gl + 16 * rr;
            ex[rr] = (p < end) ? __expf(ex[rr] - m) : 0.f;
            sum += ex[rr];
        }
#pragma unroll
        for (int o = 8; o; o >>= 1) sum += __shfl_xor_sync(hmask, sum, o);
        float invden = 1.0f / sum;

        int idx = 0;
        for (; idx + 1 < deg; idx += 2) {
            int r0 = idx >> 4,       l0 = (idx & 15) + shbase;
            int r1 = (idx + 1) >> 4, l1 = ((idx + 1) & 15) + shbase;
            float e0 = (r0 == 0) ? ex[0] : (r0 == 1) ? ex[1] : (r0 == 2) ? ex[2] : ex[3];
            int   c0 = (r0 == 0) ? sc[0] : (r0 == 1) ? sc[1] : (r0 == 2) ? sc[2] : sc[3];
            float e1 = (r1 == 0) ? ex[0] : (r1 == 1) ? ex[1] : (r1 == 2) ? ex[2] : ex[3];
            int   c1 = (r1 == 0) ? sc[0] : (r1 == 1) ? sc[1] : (r1 == 2) ? sc[2] : sc[3];
            float wa = __shfl_sync(hmask, e0, l0) * invden;
            int   sa = __shfl_sync(hmask, c0, l0);
            float wb = __shfl_sync(hmask, e1, l1) * invden;
            int   sb = __shfl_sync(hmask, c1, l1);
            F8 va = load_row8(xw4, sa, gl);
            F8 vb = load_row8(xw4, sb, gl);
#pragma unroll
            for (int q = 0; q < 8; ++q) acc[q] += wa * va.v[q] + wb * vb.v[q];
        }
        if (idx < deg) {
            int r0 = idx >> 4, l0 = (idx & 15) + shbase;
            float e0 = (r0 == 0) ? ex[0] : (r0 == 1) ? ex[1] : (r0 == 2) ? ex[2] : ex[3];
            int   c0 = (r0 == 0) ? sc[0] : (r0 == 1) ? sc[1] : (r0 == 2) ? sc[2] : sc[3];
            float wa = __shfl_sync(hmask, e0, l0) * invden;
            int   sa = __shfl_sync(hmask, c0, l0);
            F8 va = load_row8(xw4, sa, gl);
#pragma unroll
            for (int q = 0; q < 8; ++q) acc[q] += wa * va.v[q];
        }
    } else {
        float m = -1e30f;
        for (int p = beg + gl; p < end; p += 16) {
            int s = g_csr[p];
            float e = g_s[s] + dd;
            e = (e > 0.f) ? e : 0.2f * e;
            g_esc[p] = e;
            m = fmaxf(m, e);
        }
#pragma unroll
        for (int o = 8; o; o >>= 1) m = fmaxf(m, __shfl_xor_sync(hmask, m, o));
        float sum = 0.f;
        for (int p = beg + gl; p < end; p += 16) {
            float e = __expf(g_esc[p] - m);
            g_esc[p] = e;
            sum += e;
        }
#pragma unroll
        for (int o = 8; o; o >>= 1) sum += __shfl_xor_sync(hmask, sum, o);
        float invden = 1.0f / sum;
        __syncwarp(hmask);
        for (int p = beg; p < end; ++p) {
            int s = g_csr[p];
            float wgt = g_esc[p] * invden;
            F8 v = load_row8(xw4, s, gl);
#pragma unroll
            for (int q = 0; q < 8; ++q) acc[q] += wgt * v.v[q];
        }
    }

    const float4* b4 = (const float4*)bias;
    float4 b0 = b4[gl * 2], b1 = b4[gl * 2 + 1];
    acc[0] = fmaxf(acc[0] + b0.x, 0.f); acc[1] = fmaxf(acc[1] + b0.y, 0.f);
    acc[2] = fmaxf(acc[2] + b0.z, 0.f); acc[3] = fmaxf(acc[3] + b0.w, 0.f);
    acc[4] = fmaxf(acc[4] + b1.x, 0.f); acc[5] = fmaxf(acc[5] + b1.y, 0.f);
    acc[6] = fmaxf(acc[6] + b1.z, 0.f); acc[7] = fmaxf(acc[7] + b1.w, 0.f);
    store_row8(out, w, gl, acc, OUT16);
}

// ---------------- host launch ---------------------------------------------------
extern "C" void kernel_launch(void* const* d_in, const int* in_sizes, int n_in,
                              void* d_out, int out_size) {
    const float* x     = (const float*)d_in[0];
    const void*  ei    = d_in[1];
    const float* W1    = (const float*)d_in[2];
    const float* b1    = (const float*)d_in[3];
    const float* Wg1   = (const float*)d_in[4];
    const float* asrc1 = (const float*)d_in[5];
    const float* adst1 = (const float*)d_in[6];
    const float* bg1   = (const float*)d_in[7];
    const float* W2    = (const float*)d_in[8];
    const float* b2    = (const float*)d_in[9];
    const float* Wg2   = (const float*)d_in[10];
    const float* asrc2 = (const float*)d_in[11];
    const float* adst2 = (const float*)d_in[12];
    const float* bg2   = (const float*)d_in[13];
    const float* Wo    = (const float*)d_in[14];
    const float* bo    = (const float*)d_in[15];

    float* out_h = (float*)d_out;
    float* out_z = out_h + (size_t)N_NODES * HD;

    float *pA = nullptr, *pB = nullptr;
    unsigned short* pW = nullptr;
    cudaGetSymbolAddress((void**)&pA, g_bufA);
    cudaGetSymbolAddress((void**)&pB, g_bufB);
    cudaGetSymbolAddress((void**)&pW, g_wperm);
    __half* pA16 = (__half*)pA;
    __half* pB16 = (__half*)pB;
    const size_t WSTRIDE = 128 * 128;

    const int TB = 256;
    dim3 nb_hw((N_NODES + 15) / 16);
    dim3 nb_gemm((N_NODES + 127) / 128);

    // CSR build + weight conversion
    k_pre<<<NB_SCAN, 1024>>>((const unsigned int*)ei);
    k_convert_count<<<dim3(NB_E4, 2), TB>>>(ei, W1, Wg1, W2, Wg2, Wo);

    // scan (49 blocks) co-launched with K1 GEMM (391 blocks)
    k_scanK1<<<NB_SCAN + nb_gemm.x, TB>>>(x, pA16, N_NODES);
    k_fill_edges4<<<NB_E4, TB>>>();

    // Layer 1 agg: GCN (zeroes g_s/g_d for K2's att epilogue)
    gcn_agg<true><<<nb_hw, TB>>>(pA16, b1, pB16);

    // K2: xw2 = agg1 @ Wg1 (+ att dots)
    tc_gemm<128, true, true><<<nb_gemm, TB>>>(pB16, pW + WSTRIDE, nullptr, pA16, N_NODES, asrc1, adst1);
    gat_agg<true><<<nb_hw, TB>>>(pA16, bg1, pB16);

    // K3: xw3 = agg2 @ W2
    tc_gemm<128, true, true><<<nb_gemm, TB>>>(pB16, pW + 2 * WSTRIDE, nullptr, pA16, N_NODES, nullptr, nullptr);
    gcn_agg<true><<<nb_hw, TB>>>(pA16, b2, pB16);

    // K4: xw4 = agg3 @ Wg2 (+ att dots)
    tc_gemm<128, true, true><<<nb_gemm, TB>>>(pB16, pW + 3 * WSTRIDE, nullptr, pA16, N_NODES, asrc2, adst2);
    gat_agg<false><<<nb_hw, TB>>>(pA16, bg2, out_h);

    // K5: z = h @ Wo + bo (fp32 in/out)
    tc_gemm<64, false, false><<<nb_gemm, TB>>>(out_h, pW + 4 * WSTRIDE, bo, out_z, N_NODES, nullptr, nullptr);
}

// round 17
// speedup vs baseline: 1.0651x; 1.0277x over previous
#include <cuda_runtime.h>
#include <cuda_fp16.h>
#include <math.h>
#include <stdint.h>

// Problem constants
#define N_NODES 50000
#define N_EDGES 800000
#define TOT_E   850000
#define HD      128
#define NB_SCAN 49            // ceil(50000/1024)

// ---------------- device scratch --------------------------------------------
__device__ float g_bufA[(size_t)N_NODES * HD];   // fp16 xw ping
__device__ float g_bufB[(size_t)N_NODES * HD];   // fp16 xw pong
__device__ int2  g_edge[N_EDGES];                // interleaved {src, dst}
__device__ int   g_flag;
__device__ int   g_cnt[N_NODES];
__device__ int   g_off2[N_NODES + 1];
__device__ int   g_csr[TOT_E];
__device__ int   g_bpub[NB_SCAN];
__device__ float g_inv[N_NODES];
__device__ float g_s[N_NODES];
__device__ float g_d[N_NODES];
__device__ float g_esc[TOT_E];          // fallback only (deg > 64)
__device__ unsigned short g_wperm[5][128 * 128];  // fp16 fragment-permuted weights

// ---------------- warp MMA helper (fp16 inputs, fp32 accum) -------------------
__device__ __forceinline__ void mma16816(float* d, const uint32_t* a, const uint32_t* b) {
    asm volatile(
        "mma.sync.aligned.m16n8k16.row.col.f32.f16.f16.f32 "
        "{%0,%1,%2,%3}, {%4,%5,%6,%7}, {%8,%9}, {%0,%1,%2,%3};"
        : "+f"(d[0]), "+f"(d[1]), "+f"(d[2]), "+f"(d[3])
        : "r"(a[0]), "r"(a[1]), "r"(a[2]), "r"(a[3]), "r"(b[0]), "r"(b[1]));
}

// ---------------- pre: zero counts + init lookback + detect edge dtype --------
__global__ void k_pre(const unsigned int* __restrict__ w) {
    int i = blockIdx.x * 1024 + threadIdx.x;
    if (i < N_NODES) g_cnt[i] = 0;
    if (blockIdx.x == 1 && threadIdx.x < NB_SCAN) g_bpub[threadIdx.x] = -1;
    if (blockIdx.x == 0) {
        __shared__ int sflag;
        if (threadIdx.x == 0) sflag = 0;
        __syncthreads();
        if (w[2 * threadIdx.x + 1] != 0u) atomicOr(&sflag, 1);
        __syncthreads();
        if (threadIdx.x == 0) g_flag = sflag;
    }
}

// ---------------- fused: edge convert+count (y=0) | weight conversion (y=1) --
__global__ void k_convert_count(const void* __restrict__ ei,
                                const float* __restrict__ W1, const float* __restrict__ Wg1,
                                const float* __restrict__ W2, const float* __restrict__ Wg2,
                                const float* __restrict__ Wo) {
    if (blockIdx.y == 0) {
        int e = blockIdx.x * blockDim.x + threadIdx.x;
        if (e >= N_EDGES) return;
        int s, d;
        if (g_flag) {
            const int* p = (const int*)ei;
            s = p[e]; d = p[N_EDGES + e];
        } else {
            const long long* p = (const long long*)ei;
            s = (int)p[e]; d = (int)p[N_EDGES + e];
        }
        g_edge[e] = make_int2(s, d);
        atomicAdd(&g_cnt[d], 1);
    } else {
        int idx = blockIdx.x * blockDim.x + threadIdx.x;
        if (idx >= 4 * 16384 + 8192) return;
        int wsel, base, BN;
        if (idx < 16384)      { wsel = 0; base = 0;      BN = 128; }
        else if (idx < 32768) { wsel = 1; base = 16384;  BN = 128; }
        else if (idx < 49152) { wsel = 2; base = 32768;  BN = 128; }
        else if (idx < 65536) { wsel = 3; base = 49152;  BN = 128; }
        else                  { wsel = 4; base = 65536;  BN = 64;  }
        const float* W = (wsel == 0) ? W1 : (wsel == 1) ? Wg1 : (wsel == 2) ? W2
                       : (wsel == 3) ? Wg2 : Wo;
        int li = idx - base;
        int k = li / BN, n = li % BN;
        __half h = __float2half_rn(W[li]);
        int nt = n >> 3, kt = k >> 4, kk = k & 15;
        int reg = kk >> 3, klo = kk & 7;
        int lane = (n & 7) * 4 + (klo >> 1);
        int slot = ((nt * 8 + kt) * 32 + lane) * 2 + reg;
        int pos = slot * 2 + (kk & 1);
        g_wperm[wsel][pos] = __half_as_ushort(h);
    }
}

__global__ void k_fill_edges() {
    int e = blockIdx.x * blockDim.x + threadIdx.x;
    if (e < N_EDGES) {
        int2 sd = g_edge[e];                     // one LDG.64
        int pos = atomicAdd(&g_cnt[sd.y], 1);
        g_csr[pos] = sd.x;
    }
}

// ---------------- GEMM core: A frags in smem, B frags via L1 (__ldg) ----------
template <int BN, bool IN16, bool OUT16>
__device__ __forceinline__ void gemm_core(
    int row0, uint32_t* ah,
    const void* __restrict__ Xv, const unsigned short* __restrict__ wperm,
    const float* __restrict__ bias, void* __restrict__ Yv, int M,
    const float* __restrict__ a_s, const float* __restrict__ a_d) {
    constexpr int NT = BN / 16;
    int tid  = threadIdx.x;
    int wid  = tid >> 5;
    int lane = tid & 31;

    // A tile -> fragment-permuted fp16 smem
#pragma unroll
    for (int it = 0; it < 16; ++it) {
        int idx = it * 256 + tid;
        int r = idx >> 5;
        int c = (idx & 31) * 4;
        int gr = row0 + r;
        uint32_t hi0 = 0, hi1 = 0;
        if (gr < M) {
            if (IN16) {
                uint2 u = ((const uint2*)Xv)[(size_t)gr * 32 + (idx & 31)];
                hi0 = u.x; hi1 = u.y;
            } else {
                float4 v = ((const float4*)Xv)[(size_t)gr * 32 + (idx & 31)];
                __half2 h0 = __floats2half2_rn(v.x, v.y);
                __half2 h1 = __floats2half2_rn(v.z, v.w);
                hi0 = *reinterpret_cast<uint32_t*>(&h0);
                hi1 = *reinterpret_cast<uint32_t*>(&h1);
            }
        }
        int mt = r >> 4, rr = r & 15;
        int kt = c >> 4, cc = c & 15;
        int reg = ((cc >> 3) << 1) | (rr >> 3);
        int ln0 = (rr & 7) * 4 + ((cc & 7) >> 1);
        int base = (mt * 8 + kt) * 32;
        ah[(base + ln0) * 4 + reg]     = hi0;
        ah[(base + ln0 + 1) * 4 + reg] = hi1;
    }
    __syncthreads();

    int wm = wid & 3;
    int wn = wid >> 2;
    float acc[2][NT][4];
#pragma unroll
    for (int i = 0; i < 2; ++i)
#pragma unroll
        for (int j = 0; j < NT; ++j)
#pragma unroll
            for (int q = 0; q < 4; ++q) acc[i][j][q] = 0.f;

    const uint4* Ah = (const uint4*)ah;
    const uint2* Bg = (const uint2*)wperm;     // L1-resident after first k-step
#pragma unroll
    for (int kt = 0; kt < 8; ++kt) {
        uint4 a0 = Ah[((wm * 2 + 0) * 8 + kt) * 32 + lane];
        uint4 a1 = Ah[((wm * 2 + 1) * 8 + kt) * 32 + lane];
        uint2 b[NT];
#pragma unroll
        for (int j = 0; j < NT; ++j)
            b[j] = __ldg(&Bg[((wn * NT + j) * 8 + kt) * 32 + lane]);
#pragma unroll
        for (int j = 0; j < NT; ++j) {
            mma16816(acc[0][j], (const uint32_t*)&a0, (const uint32_t*)&b[j]);
            mma16816(acc[1][j], (const uint32_t*)&a1, (const uint32_t*)&b[j]);
        }
    }

    int rbase = row0 + wm * 32 + (lane >> 2);
    int cbase = wn * NT * 8 + (lane & 3) * 2;
#pragma unroll
    for (int i = 0; i < 2; ++i) {
        int r = rbase + i * 16;
#pragma unroll
        for (int j = 0; j < NT; ++j) {
            int cc = cbase + j * 8;
            float bx = 0.f, by = 0.f;
            if (bias) { bx = bias[cc]; by = bias[cc + 1]; }
            if (OUT16) {
                __half* Y = (__half*)Yv;
                if (r < M)
                    *(__half2*)&Y[(size_t)r * BN + cc] =
                        __floats2half2_rn(acc[i][j][0] + bx, acc[i][j][1] + by);
                if (r + 8 < M)
                    *(__half2*)&Y[(size_t)(r + 8) * BN + cc] =
                        __floats2half2_rn(acc[i][j][2] + bx, acc[i][j][3] + by);
            } else {
                float* Y = (float*)Yv;
                if (r < M) {
                    float2 v0 = make_float2(acc[i][j][0] + bx, acc[i][j][1] + by);
                    *(float2*)&Y[(size_t)r * BN + cc] = v0;
                }
                if (r + 8 < M) {
                    float2 v1 = make_float2(acc[i][j][2] + bx, acc[i][j][3] + by);
                    *(float2*)&Y[(size_t)(r + 8) * BN + cc] = v1;
                }
            }
        }
    }

    if (a_s) {
        float ps[2][2] = {{0.f, 0.f}, {0.f, 0.f}};
        float pd[2][2] = {{0.f, 0.f}, {0.f, 0.f}};
#pragma unroll
        for (int i = 0; i < 2; ++i)
#pragma unroll
            for (int j = 0; j < NT; ++j) {
                int cc = cbase + j * 8;
                float as0 = a_s[cc], as1 = a_s[cc + 1];
                float ad0 = a_d[cc], ad1 = a_d[cc + 1];
                ps[i][0] += acc[i][j][0] * as0 + acc[i][j][1] * as1;
                pd[i][0] += acc[i][j][0] * ad0 + acc[i][j][1] * ad1;
                ps[i][1] += acc[i][j][2] * as0 + acc[i][j][3] * as1;
                pd[i][1] += acc[i][j][2] * ad0 + acc[i][j][3] * ad1;
            }
#pragma unroll
        for (int i = 0; i < 2; ++i)
#pragma unroll
            for (int h = 0; h < 2; ++h) {
                float s = ps[i][h], d = pd[i][h];
                s += __shfl_xor_sync(0xffffffffu, s, 1);
                s += __shfl_xor_sync(0xffffffffu, s, 2);
                d += __shfl_xor_sync(0xffffffffu, d, 1);
                d += __shfl_xor_sync(0xffffffffu, d, 2);
                if ((lane & 3) == 0) {
                    int r = row0 + wm * 32 + i * 16 + h * 8 + (lane >> 2);
                    if (r < M) {
                        atomicAdd(&g_s[r], s);
                        atomicAdd(&g_d[r], d);
                    }
                }
            }
    }
}

// ---------------- standalone GEMM kernel ---------------------------------------
template <int BN, bool IN16, bool OUT16>
__global__ void __launch_bounds__(256)
tc_gemm(const void* __restrict__ Xv, const unsigned short* __restrict__ wperm,
        const float* __restrict__ bias, void* __restrict__ Yv, int M,
        const float* __restrict__ a_s, const float* __restrict__ a_d) {
    __shared__ uint32_t ah[8192];   // 32 KB A fragments
    gemm_core<BN, IN16, OUT16>(blockIdx.x * 128, ah, Xv, wperm, bias, Yv, M, a_s, a_d);
}

// ---------------- co-launched scan (blocks 0..48) + K1 GEMM (blocks 49..) ------
__global__ void __launch_bounds__(256)
k_scanK1(const float* __restrict__ x, void* __restrict__ Yv, int M) {
    __shared__ uint32_t ah[8192];
    if (blockIdx.x < NB_SCAN) {
        __shared__ int sdat[256];
        __shared__ int s_prefix;
        int t = threadIdx.x;
        int blk = blockIdx.x;
        int base = blk * 1024 + t * 4;
        int v[4];
        int lsum = 0;
#pragma unroll
        for (int q = 0; q < 4; ++q) {
            int i = base + q;
            v[q] = (i < N_NODES) ? g_cnt[i] + 1 : 0;   // +1 = self loop
            lsum += v[q];
        }
        sdat[t] = lsum;
        __syncthreads();
        for (int off = 1; off < 256; off <<= 1) {
            int xx = (t >= off) ? sdat[t - off] : 0;
            __syncthreads();
            sdat[t] += xx;
            __syncthreads();
        }
        int incl = sdat[t];
        if (t == 255) *(volatile int*)&g_bpub[blk] = incl;
        if (t < 32) {
            int pre = 0;
            for (int j = t; j < blk; j += 32) {
                int vv;
                do { vv = *(volatile int*)&g_bpub[j]; } while (vv == -1);
                pre += vv;
            }
#pragma unroll
            for (int o = 16; o; o >>= 1) pre += __shfl_xor_sync(0xffffffffu, pre, o);
            if (t == 0) s_prefix = pre;
        }
        __syncthreads();
        int b = s_prefix + incl - lsum;
#pragma unroll
        for (int q = 0; q < 4; ++q) {
            int i = base + q;
            if (i < N_NODES) {
                g_off2[i] = b;
                g_csr[b] = i;          // self loop
                g_cnt[i] = b + 1;      // fill cursor
                g_inv[i] = rsqrtf((float)v[q]);
                if (i == N_NODES - 1) g_off2[N_NODES] = b + v[q];
                b += v[q];
            }
        }
    } else {
        gemm_core<128, false, true>((blockIdx.x - NB_SCAN) * 128, ah,
                                    x, g_wperm[0], nullptr, Yv, M, nullptr, nullptr);
    }
}

// ---------------- half-warp gather helpers -------------------------------------
struct F8 { float v[8]; };

__device__ __forceinline__ F8 load_row8(const uint4* xw4, int s, int gl) {
    uint4 u = xw4[(size_t)s * 16 + gl];
    F8 r;
    float2 f;
    f = __half22float2(*reinterpret_cast<__half2*>(&u.x)); r.v[0] = f.x; r.v[1] = f.y;
    f = __half22float2(*reinterpret_cast<__half2*>(&u.y)); r.v[2] = f.x; r.v[3] = f.y;
    f = __half22float2(*reinterpret_cast<__half2*>(&u.z)); r.v[4] = f.x; r.v[5] = f.y;
    f = __half22float2(*reinterpret_cast<__half2*>(&u.w)); r.v[6] = f.x; r.v[7] = f.y;
    return r;
}

__device__ __forceinline__ void store_row8(void* out, int w, int gl,
                                           const float* a, bool out16) {
    if (out16) {
        uint4 u;
        __half2 h;
        h = __floats2half2_rn(a[0], a[1]); u.x = *reinterpret_cast<uint32_t*>(&h);
        h = __floats2half2_rn(a[2], a[3]); u.y = *reinterpret_cast<uint32_t*>(&h);
        h = __floats2half2_rn(a[4], a[5]); u.z = *reinterpret_cast<uint32_t*>(&h);
        h = __floats2half2_rn(a[6], a[7]); u.w = *reinterpret_cast<uint32_t*>(&h);
        ((uint4*)out)[(size_t)w * 16 + gl] = u;
    } else {
        float* o = (float*)out + (size_t)w * 128 + gl * 8;
        *(float4*)o       = make_float4(a[0], a[1], a[2], a[3]);
        *(float4*)(o + 4) = make_float4(a[4], a[5], a[6], a[7]);
    }
}

// ---------------- GCN aggregate: half-warp per node ----------------------------
template <bool OUT16>
__global__ void gcn_agg(const __half* __restrict__ xw,
                        const float* __restrict__ bias,
                        void* __restrict__ out) {
    int gwarp = (blockIdx.x * blockDim.x + threadIdx.x) >> 5;
    int lane = threadIdx.x & 31;
    int grp = lane >> 4, gl = lane & 15;
    int w = gwarp * 2 + grp;
    if (w >= N_NODES) return;
    if (gl == 0) { g_s[w] = 0.f; g_d[w] = 0.f; }
    int beg = g_off2[w], end = g_off2[w + 1];
    float invd = g_inv[w];
    const uint4* xw4 = (const uint4*)xw;
    float acc[8] = {0.f, 0.f, 0.f, 0.f, 0.f, 0.f, 0.f, 0.f};
    int p = beg;
    for (; p + 1 < end; p += 2) {
        int s0 = g_csr[p], s1 = g_csr[p + 1];
        float c0 = invd * g_inv[s0];
        float c1 = invd * g_inv[s1];
        F8 v0 = load_row8(xw4, s0, gl);
        F8 v1 = load_row8(xw4, s1, gl);
#pragma unroll
        for (int q = 0; q < 8; ++q) acc[q] += c0 * v0.v[q] + c1 * v1.v[q];
    }
    if (p < end) {
        int s0 = g_csr[p];
        float c0 = invd * g_inv[s0];
        F8 v0 = load_row8(xw4, s0, gl);
#pragma unroll
        for (int q = 0; q < 8; ++q) acc[q] += c0 * v0.v[q];
    }
    const float4* b4 = (const float4*)bias;
    float4 b0 = b4[gl * 2], b1 = b4[gl * 2 + 1];
    acc[0] = fmaxf(acc[0] + b0.x, 0.f); acc[1] = fmaxf(acc[1] + b0.y, 0.f);
    acc[2] = fmaxf(acc[2] + b0.z, 0.f); acc[3] = fmaxf(acc[3] + b0.w, 0.f);
    acc[4] = fmaxf(acc[4] + b1.x, 0.f); acc[5] = fmaxf(acc[5] + b1.y, 0.f);
    acc[6] = fmaxf(acc[6] + b1.z, 0.f); acc[7] = fmaxf(acc[7] + b1.w, 0.f);
    store_row8(out, w, gl, acc, OUT16);
}

// ---------------- GAT aggregate: half-warp per node, register-cached -----------
template <bool OUT16>
__global__ void gat_agg(const __half* __restrict__ xw,
                        const float* __restrict__ bias,
                        void* __restrict__ out) {
    int gwarp = (blockIdx.x * blockDim.x + threadIdx.x) >> 5;
    int lane = threadIdx.x & 31;
    int grp = lane >> 4, gl = lane & 15;
    int shbase = grp << 4;
    unsigned hmask = 0xFFFFu << shbase;    // exact half-warp convergence group
    int w = gwarp * 2 + grp;
    if (w >= N_NODES) return;
    int beg = g_off2[w], end = g_off2[w + 1];
    int deg = end - beg;
    float dd = g_d[w];
    const uint4* xw4 = (const uint4*)xw;
    float acc[8] = {0.f, 0.f, 0.f, 0.f, 0.f, 0.f, 0.f, 0.f};

    if (deg <= 64) {
        int sc[4];
        float ex[4];
        float m = -1e30f;
#pragma unroll
        for (int rr = 0; rr < 4; ++rr) {
            int p = beg + gl + 16 * rr;
            sc[rr] = 0; ex[rr] = -1e30f;
            if (p < end) {
                sc[rr] = g_csr[p];
                float t = g_s[sc[rr]] + dd;
                ex[rr] = (t > 0.f) ? t : 0.2f * t;
            }
            m = fmaxf(m, ex[rr]);
        }
#pragma unroll
        for (int o = 8; o; o >>= 1) m = fmaxf(m, __shfl_xor_sync(hmask, m, o));
        float sum = 0.f;
#pragma unroll
        for (int rr = 0; rr < 4; ++rr) {
            int p = beg + gl + 16 * rr;
            ex[rr] = (p < end) ? __expf(ex[rr] - m) : 0.f;
            sum += ex[rr];
        }
#pragma unroll
        for (int o = 8; o; o >>= 1) sum += __shfl_xor_sync(hmask, sum, o);
        float invden = 1.0f / sum;

        int idx = 0;
        for (; idx + 1 < deg; idx += 2) {
            int r0 = idx >> 4,       l0 = (idx & 15) + shbase;
            int r1 = (idx + 1) >> 4, l1 = ((idx + 1) & 15) + shbase;
            float e0 = (r0 == 0) ? ex[0] : (r0 == 1) ? ex[1] : (r0 == 2) ? ex[2] : ex[3];
            int   c0 = (r0 == 0) ? sc[0] : (r0 == 1) ? sc[1] : (r0 == 2) ? sc[2] : sc[3];
            float e1 = (r1 == 0) ? ex[0] : (r1 == 1) ? ex[1] : (r1 == 2) ? ex[2] : ex[3];
            int   c1 = (r1 == 0) ? sc[0] : (r1 == 1) ? sc[1] : (r1 == 2) ? sc[2] : sc[3];
            float wa = __shfl_sync(hmask, e0, l0) * invden;
            int   sa = __shfl_sync(hmask, c0, l0);
            float wb = __shfl_sync(hmask, e1, l1) * invden;
            int   sb = __shfl_sync(hmask, c1, l1);
            F8 va = load_row8(xw4, sa, gl);
            F8 vb = load_row8(xw4, sb, gl);
#pragma unroll
            for (int q = 0; q < 8; ++q) acc[q] += wa * va.v[q] + wb * vb.v[q];
        }
        if (idx < deg) {
            int r0 = idx >> 4, l0 = (idx & 15) + shbase;
            float e0 = (r0 == 0) ? ex[0] : (r0 == 1) ? ex[1] : (r0 == 2) ? ex[2] : ex[3];
            int   c0 = (r0 == 0) ? sc[0] : (r0 == 1) ? sc[1] : (r0 == 2) ? sc[2] : sc[3];
            float wa = __shfl_sync(hmask, e0, l0) * invden;
            int   sa = __shfl_sync(hmask, c0, l0);
            F8 va = load_row8(xw4, sa, gl);
#pragma unroll
            for (int q = 0; q < 8; ++q) acc[q] += wa * va.v[q];
        }
    } else {
        float m = -1e30f;
        for (int p = beg + gl; p < end; p += 16) {
            int s = g_csr[p];
            float e = g_s[s] + dd;
            e = (e > 0.f) ? e : 0.2f * e;
            g_esc[p] = e;
            m = fmaxf(m, e);
        }
#pragma unroll
        for (int o = 8; o; o >>= 1) m = fmaxf(m, __shfl_xor_sync(hmask, m, o));
        float sum = 0.f;
        for (int p = beg + gl; p < end; p += 16) {
            float e = __expf(g_esc[p] - m);
            g_esc[p] = e;
            sum += e;
        }
#pragma unroll
        for (int o = 8; o; o >>= 1) sum += __shfl_xor_sync(hmask, sum, o);
        float invden = 1.0f / sum;
        __syncwarp(hmask);
        for (int p = beg; p < end; ++p) {
            int s = g_csr[p];
            float wgt = g_esc[p] * invden;
            F8 v = load_row8(xw4, s, gl);
#pragma unroll
            for (int q = 0; q < 8; ++q) acc[q] += wgt * v.v[q];
        }
    }

    const float4* b4 = (const float4*)bias;
    float4 b0 = b4[gl * 2], b1 = b4[gl * 2 + 1];
    acc[0] = fmaxf(acc[0] + b0.x, 0.f); acc[1] = fmaxf(acc[1] + b0.y, 0.f);
    acc[2] = fmaxf(acc[2] + b0.z, 0.f); acc[3] = fmaxf(acc[3] + b0.w, 0.f);
    acc[4] = fmaxf(acc[4] + b1.x, 0.f); acc[5] = fmaxf(acc[5] + b1.y, 0.f);
    acc[6] = fmaxf(acc[6] + b1.z, 0.f); acc[7] = fmaxf(acc[7] + b1.w, 0.f);
    store_row8(out, w, gl, acc, OUT16);
}

// ---------------- host launch ---------------------------------------------------
extern "C" void kernel_launch(void* const* d_in, const int* in_sizes, int n_in,
                              void* d_out, int out_size) {
    const float* x     = (const float*)d_in[0];
    const void*  ei    = d_in[1];
    const float* W1    = (const float*)d_in[2];
    const float* b1    = (const float*)d_in[3];
    const float* Wg1   = (const float*)d_in[4];
    const float* asrc1 = (const float*)d_in[5];
    const float* adst1 = (const float*)d_in[6];
    const float* bg1   = (const float*)d_in[7];
    const float* W2    = (const float*)d_in[8];
    const float* b2    = (const float*)d_in[9];
    const float* Wg2   = (const float*)d_in[10];
    const float* asrc2 = (const float*)d_in[11];
    const float* adst2 = (const float*)d_in[12];
    const float* bg2   = (const float*)d_in[13];
    const float* Wo    = (const float*)d_in[14];
    const float* bo    = (const float*)d_in[15];

    float* out_h = (float*)d_out;
    float* out_z = out_h + (size_t)N_NODES * HD;

    float *pA = nullptr, *pB = nullptr;
    unsigned short* pW = nullptr;
    cudaGetSymbolAddress((void**)&pA, g_bufA);
    cudaGetSymbolAddress((void**)&pB, g_bufB);
    cudaGetSymbolAddress((void**)&pW, g_wperm);
    __half* pA16 = (__half*)pA;
    __half* pB16 = (__half*)pB;
    const size_t WSTRIDE = 128 * 128;

    const int TB = 256;
    dim3 nb_edge((N_EDGES + TB - 1) / TB);
    dim3 nb_hw((N_NODES + 15) / 16);
    dim3 nb_gemm((N_NODES + 127) / 128);

    // CSR build + weight conversion
    k_pre<<<NB_SCAN, 1024>>>((const unsigned int*)ei);
    k_convert_count<<<dim3(nb_edge.x, 2), TB>>>(ei, W1, Wg1, W2, Wg2, Wo);

    // scan (49 blocks) co-launched with K1 GEMM (391 blocks)
    k_scanK1<<<NB_SCAN + nb_gemm.x, TB>>>(x, pA16, N_NODES);
    k_fill_edges<<<nb_edge, TB>>>();

    // Layer 1 agg: GCN (zeroes g_s/g_d for K2's att epilogue)
    gcn_agg<true><<<nb_hw, TB>>>(pA16, b1, pB16);

    // K2: xw2 = agg1 @ Wg1 (+ att dots)
    tc_gemm<128, true, true><<<nb_gemm, TB>>>(pB16, pW + WSTRIDE, nullptr, pA16, N_NODES, asrc1, adst1);
    gat_agg<true><<<nb_hw, TB>>>(pA16, bg1, pB16);

    // K3: xw3 = agg2 @ W2
    tc_gemm<128, true, true><<<nb_gemm, TB>>>(pB16, pW + 2 * WSTRIDE, nullptr, pA16, N_NODES, nullptr, nullptr);
    gcn_agg<true><<<nb_hw, TB>>>(pA16, b2, pB16);

    // K4: xw4 = agg3 @ Wg2 (+ att dots)
    tc_gemm<128, true, true><<<nb_gemm, TB>>>(pB16, pW + 3 * WSTRIDE, nullptr, pA16, N_NODES, asrc2, adst2);
    gat_agg<false><<<nb_hw, TB>>>(pA16, bg2, out_h);

    // K5: z = h @ Wo + bo (fp32 in/out)
    tc_gemm<64, false, false><<<nb_gemm, TB>>>(out_h, pW + 4 * WSTRIDE, bo, out_z, N_NODES, nullptr, nullptr);
}